// round 4
// baseline (speedup 1.0000x reference)
#include <cuda_runtime.h>
#include <math.h>

#define Nn 50000
#define Dd 128
#define Tt 4
#define Ee 150000
#define Hh 8
#define E4  (Tt * Ee)
#define TN  (Tt * Nn)
#define NEG_SLOPE 0.2f
#define EPSF 1e-6f

// ---------------- scratch (static device globals; no allocation) ----------------
__device__ float g_h[Nn*Dd];
__device__ float g_k[Nn*Dd];
__device__ float g_q[Nn*Dd];
__device__ float g_v[Nn*Dd];
__device__ float g_tmp[Nn*Dd];
__device__ float g_al[TN*Hh];
__device__ float g_ar[TN*Hh];
__device__ float g_big1[(size_t)Tt*Nn*Dd];   // GAT: xw per type | HGT: qA
__device__ float g_big2[(size_t)Tt*Nn*Dd];   // HGT: vM
__device__ int   g_deg[TN];
__device__ int   g_off[TN];
__device__ int   g_cur[TN];
__device__ int   g_csr[E4];                  // src ids bucketed by (type,dst)

// ---------------- device helpers ----------------
__device__ __forceinline__ float geluf(float x) {
    return 0.5f * x * (1.0f + erff(x * 0.7071067811865476f));
}
__device__ __forceinline__ const int* pick_ei(int t, const int* e0, const int* e1,
                                              const int* e2, const int* e3) {
    return (t == 0) ? e0 : (t == 1) ? e1 : (t == 2) ? e2 : e3;
}

// ---------------- elementwise ----------------
__global__ void add3k(const float4* __restrict__ a, const float4* __restrict__ b,
                      const float4* __restrict__ c, float4* __restrict__ o, int n4) {
    int i = blockIdx.x*blockDim.x + threadIdx.x;
    if (i < n4) {
        float4 x = a[i], y = b[i], z = c[i];
        o[i] = make_float4(x.x+y.x+z.x, x.y+y.y+z.y, x.z+y.z+z.z, x.w+y.w+z.w);
    }
}
__global__ void zeroint(int* __restrict__ p, int n) {
    int i = blockIdx.x*blockDim.x + threadIdx.x;
    if (i < n) p[i] = 0;
}

// ---------------- CSR build (once; edge index is launch-invariant) ----------------
__global__ void deg_k(const int* __restrict__ e0, const int* __restrict__ e1,
                      const int* __restrict__ e2, const int* __restrict__ e3,
                      int* __restrict__ deg) {
    int idx = blockIdx.x*blockDim.x + threadIdx.x;
    if (idx >= E4) return;
    int t = idx / Ee, e = idx - t*Ee;
    const int* ei = pick_ei(t, e0, e1, e2, e3);
    atomicAdd(&deg[t*Nn + ei[Ee + e]], 1);
}

// single-block exclusive scan over TN=200000 ints (sum per type = Ee, so the
// global scan lands type-t buckets exactly in csr[t*Ee, (t+1)*Ee)).
__global__ void scan_k(const int* __restrict__ deg, int* __restrict__ off,
                       int* __restrict__ cur) {
    const int TH = 1024, CH = (TN + TH - 1) / TH;
    int tid = threadIdx.x;
    int base = tid * CH;
    int sum = 0;
    for (int i = 0; i < CH; i++) { int gI = base + i; if (gI < TN) sum += deg[gI]; }
    int lane = tid & 31, w = tid >> 5;
    int v = sum;
    #pragma unroll
    for (int o = 1; o < 32; o <<= 1) { int u = __shfl_up_sync(~0u, v, o); if (lane >= o) v += u; }
    __shared__ int ws[32];
    if (lane == 31) ws[w] = v;
    __syncthreads();
    if (w == 0) {
        int x = ws[lane];
        #pragma unroll
        for (int o = 1; o < 32; o <<= 1) { int u = __shfl_up_sync(~0u, x, o); if (lane >= o) x += u; }
        ws[lane] = x;
    }
    __syncthreads();
    int run = v - sum + (w > 0 ? ws[w-1] : 0);
    for (int i = 0; i < CH; i++) {
        int gI = base + i;
        if (gI < TN) { off[gI] = run; cur[gI] = run; run += deg[gI]; }
    }
}

__global__ void fill_k(const int* __restrict__ e0, const int* __restrict__ e1,
                       const int* __restrict__ e2, const int* __restrict__ e3,
                       int* __restrict__ cur, int* __restrict__ csr) {
    int idx = blockIdx.x*blockDim.x + threadIdx.x;
    if (idx >= E4) return;
    int t = idx / Ee, e = idx - t*Ee;
    const int* ei = pick_ei(t, e0, e1, e2, e3);
    int src = ei[e], dst = ei[Ee + e];
    int slot = atomicAdd(&cur[t*Nn + dst], 1);
    csr[slot] = src;
}

// ---------------- GEMM: C[Mx128] = A[Mx128] @ W[128x128] (+ bias) ----------------
template <bool ALAR>
__global__ void gemm128(const float* __restrict__ A, const float* __restrict__ Wbase,
                        const float* __restrict__ bias, float* __restrict__ Cbase,
                        const float* __restrict__ asb, const float* __restrict__ adb,
                        float* __restrict__ al, float* __restrict__ ar, int M) {
    __shared__ float As[64][128];
    const int t = blockIdx.y;
    const float* W = Wbase + (size_t)t*Dd*Dd;
    float* C = Cbase + (size_t)t*M*Dd;
    const int block_row = blockIdx.x * 64;
    const int tid = threadIdx.x;
    for (int i = tid; i < 64*32; i += 256) {
        int r = i >> 5, c4 = i & 31;
        int gr = block_row + r;
        float4 val = (gr < M) ? *(const float4*)(A + (size_t)gr*Dd + c4*4) : make_float4(0,0,0,0);
        *(float4*)(&As[r][c4*4]) = val;
    }
    __syncthreads();
    const int tx = tid & 31, ty = tid >> 5;
    const int c = tx * 4;
    float4 acc[8];
    #pragma unroll
    for (int i = 0; i < 8; i++) acc[i] = make_float4(0,0,0,0);
    #pragma unroll 4
    for (int k = 0; k < 128; k++) {
        float4 w = *(const float4*)(W + k*Dd + c);
        #pragma unroll
        for (int i = 0; i < 8; i++) {
            float a = As[ty*8 + i][k];
            acc[i].x += a*w.x; acc[i].y += a*w.y; acc[i].z += a*w.z; acc[i].w += a*w.w;
        }
    }
    float4 b4 = bias ? *(const float4*)(bias + c) : make_float4(0,0,0,0);
    #pragma unroll
    for (int i = 0; i < 8; i++) {
        int gr = block_row + ty*8 + i;
        if (gr < M) {
            float4 o = acc[i];
            o.x += b4.x; o.y += b4.y; o.z += b4.z; o.w += b4.w;
            *(float4*)(C + (size_t)gr*Dd + c) = o;
        }
    }
    if (ALAR) {
        float4 s4 = *(const float4*)(asb + t*Dd + c);
        float4 d4 = *(const float4*)(adb + t*Dd + c);
        #pragma unroll
        for (int i = 0; i < 8; i++) {
            float pa = acc[i].x*s4.x + acc[i].y*s4.y + acc[i].z*s4.z + acc[i].w*s4.w;
            float pr = acc[i].x*d4.x + acc[i].y*d4.y + acc[i].z*d4.z + acc[i].w*d4.w;
            pa += __shfl_xor_sync(0xffffffffu, pa, 1);
            pa += __shfl_xor_sync(0xffffffffu, pa, 2);
            pr += __shfl_xor_sync(0xffffffffu, pr, 1);
            pr += __shfl_xor_sync(0xffffffffu, pr, 2);
            int gr = block_row + ty*8 + i;
            if (gr < M && (tx & 3) == 0) {
                int o = ((t*Nn) + gr)*Hh + (tx >> 2);
                al[o] = pa;
                ar[o] = pr;
            }
        }
    }
}

// ---------------- GAT gather (one warp per dst node; fuses softmax-normalize,
// per-type sum, bias, rmsnorm residual, gelu). No atomics. ----------------
__global__ void gat_gather(const int* __restrict__ csr, const int* __restrict__ off,
                           const int* __restrict__ deg, const float* __restrict__ al,
                           const float* __restrict__ ar, const float* __restrict__ xw,
                           const float* __restrict__ b, const float* __restrict__ g,
                           float* __restrict__ h) {
    int gt = blockIdx.x*blockDim.x + threadIdx.x;
    int n = gt >> 5, lane = gt & 31;
    if (n >= Nn) return;
    int hh = lane >> 2;

    float4 a4;
    {
        float4 b0 = *(const float4*)(b + lane*4);
        float4 b1 = *(const float4*)(b + Dd + lane*4);
        float4 b2 = *(const float4*)(b + 2*Dd + lane*4);
        float4 b3 = *(const float4*)(b + 3*Dd + lane*4);
        a4 = make_float4(b0.x+b1.x+b2.x+b3.x, b0.y+b1.y+b2.y+b3.y,
                         b0.z+b1.z+b2.z+b3.z, b0.w+b1.w+b2.w+b3.w);
    }

    #pragma unroll
    for (int t = 0; t < Tt; t++) {
        int i = t*Nn + n;
        float arn = ar[(size_t)i*Hh + hh];
        // self loop (src = dst = n)
        float v = al[(size_t)i*Hh + hh] + arn;
        v = v > 0.f ? v : NEG_SLOPE*v;
        float p = expf(v);
        float s = p;
        float4 x = *(const float4*)(xw + (size_t)i*Dd + lane*4);
        float4 f = make_float4(x.x*p, x.y*p, x.z*p, x.w*p);

        int st = off[i], dg = deg[i];
        for (int j0 = 0; j0 < dg; j0 += 32) {
            int myS = (j0 + lane < dg) ? csr[st + j0 + lane] : 0;
            int cnt = min(32, dg - j0);
            for (int j = 0; j < cnt; j++) {
                int src = __shfl_sync(0xffffffffu, myS, j);
                float vv = al[((size_t)t*Nn + src)*Hh + hh] + arn;
                vv = vv > 0.f ? vv : NEG_SLOPE*vv;
                float pp = expf(vv);
                s += pp;
                float4 xx = *(const float4*)(xw + ((size_t)t*Nn + src)*Dd + lane*4);
                f.x += xx.x*pp; f.y += xx.y*pp; f.z += xx.z*pp; f.w += xx.w*pp;
            }
        }
        float inv = 1.f / s;   // s >= exp(self) > 0
        a4.x += f.x*inv; a4.y += f.y*inv; a4.z += f.z*inv; a4.w += f.w*inv;
    }

    // rmsnorm(a4, g) + residual gelu, warp-wide over 128 dims
    float ss = a4.x*a4.x + a4.y*a4.y + a4.z*a4.z + a4.w*a4.w;
    #pragma unroll
    for (int o = 16; o > 0; o >>= 1) ss += __shfl_xor_sync(0xffffffffu, ss, o);
    float inv = rsqrtf(ss * (1.0f/Dd) + EPSF);
    float4 g4 = *(const float4*)(g + lane*4);
    float4 h4 = *(const float4*)(h + (size_t)n*Dd + lane*4);
    float4 o4;
    o4.x = geluf(h4.x + g4.x*a4.x*inv);
    o4.y = geluf(h4.y + g4.y*a4.y*inv);
    o4.z = geluf(h4.z + g4.z*a4.z*inv);
    o4.w = geluf(h4.w + g4.w*a4.w*inv);
    *(float4*)(h + (size_t)n*Dd + lane*4) = o4;
}

// ---------------- HGT ----------------
template <bool RT>
__global__ void hgt_rel(const float* __restrict__ x, const float* __restrict__ R,
                        float* __restrict__ out) {
    int idx = blockIdx.x*blockDim.x + threadIdx.x;
    if (idx >= Nn*Tt*Hh) return;
    int h = idx & 7, t = (idx >> 3) & 3, n = idx >> 5;
    const float* xp = x + (size_t)n*Dd + h*16;
    const float* Rp = R + (t*Hh + h)*256;
    float xr[16];
    #pragma unroll
    for (int i = 0; i < 4; i++) ((float4*)xr)[i] = ((const float4*)xp)[i];
    float o[16];
    #pragma unroll
    for (int i = 0; i < 16; i++) o[i] = 0.f;
    #pragma unroll
    for (int j = 0; j < 16; j++) {
        float xj = xr[j];
        #pragma unroll
        for (int i = 0; i < 16; i++)
            o[i] += xj * (RT ? Rp[i*16 + j] : Rp[j*16 + i]);
    }
    float* op = out + ((size_t)n*Tt + t)*Dd + h*16;
    #pragma unroll
    for (int i = 0; i < 4; i++) ((float4*)op)[i] = ((float4*)o)[i];
}

// HGT gather (one warp per dst; joint softmax across types in registers;
// fuses normalize + gelu into tmp). No atomics.
__global__ void hgt_gather(const int* __restrict__ csr, const int* __restrict__ off,
                           const int* __restrict__ deg, const float* __restrict__ k,
                           const float* __restrict__ qA, const float* __restrict__ prel,
                           const float* __restrict__ vM, float* __restrict__ out) {
    int gt = blockIdx.x*blockDim.x + threadIdx.x;
    int n = gt >> 5, lane = gt & 31;
    if (n >= Nn) return;
    int hh = lane >> 2;

    float4 acc = make_float4(0,0,0,0);
    float s = 0.f;

    #pragma unroll
    for (int t = 0; t < Tt; t++) {
        int i = t*Nn + n;
        float4 qv = *(const float4*)(qA + ((size_t)n*Tt + t)*Dd + lane*4);
        float pr = prel[t*Hh + hh] * 0.25f;   // / sqrt(16)
        int st = off[i], dg = deg[i];
        for (int j0 = 0; j0 < dg; j0 += 32) {
            int myS = (j0 + lane < dg) ? csr[st + j0 + lane] : 0;
            int cnt = min(32, dg - j0);
            for (int j = 0; j < cnt; j++) {
                int src = __shfl_sync(0xffffffffu, myS, j);
                float4 kv = *(const float4*)(k + (size_t)src*Dd + lane*4);
                float part = kv.x*qv.x + kv.y*qv.y + kv.z*qv.z + kv.w*qv.w;
                part += __shfl_xor_sync(0xffffffffu, part, 1);
                part += __shfl_xor_sync(0xffffffffu, part, 2);
                float p = expf(part * pr);
                s += p;
                float4 vm = *(const float4*)(vM + ((size_t)src*Tt + t)*Dd + lane*4);
                acc.x += vm.x*p; acc.y += vm.y*p; acc.z += vm.z*p; acc.w += vm.w*p;
            }
        }
    }
    float inv = 1.f / (s > 0.f ? s : 1.f);
    float4 o4;
    o4.x = geluf(acc.x*inv);
    o4.y = geluf(acc.y*inv);
    o4.z = geluf(acc.z*inv);
    o4.w = geluf(acc.w*inv);
    *(float4*)(out + (size_t)n*Dd + lane*4) = o4;
}

// out = gelu(h + rmsnorm(beta*o + (1-beta)*h, g)),  beta = sigmoid(skip)
__global__ void hgt_post(const float* __restrict__ h, const float* __restrict__ o,
                         const float* __restrict__ g, const float* __restrict__ skip,
                         float* __restrict__ out) {
    int n = blockIdx.x, d = threadIdx.x;
    float beta = 1.f / (1.f + expf(-skip[0]));
    int i = n*Dd + d;
    float hv = h[i];
    float u = beta*o[i] + (1.f - beta)*hv;
    float ss = u*u;
    #pragma unroll
    for (int off = 16; off > 0; off >>= 1) ss += __shfl_xor_sync(0xffffffffu, ss, off);
    __shared__ float sw[4];
    if ((d & 31) == 0) sw[d >> 5] = ss;
    __syncthreads();
    float tot = sw[0] + sw[1] + sw[2] + sw[3];
    float y = g[d] * u * rsqrtf(tot * (1.0f/Dd) + EPSF);
    out[i] = geluf(hv + y);
}

// ---------------- host launch ----------------
extern "C" void kernel_launch(void* const* d_in, const int* in_sizes, int n_in,
                              void* d_out, int out_size) {
    const float* zL  = (const float*)d_in[0];
    const float* zH  = (const float*)d_in[1];
    const float* xe  = (const float*)d_in[2];
    const float* W1  = (const float*)d_in[3];
    const float* as1 = (const float*)d_in[4];
    const float* ad1 = (const float*)d_in[5];
    const float* b1  = (const float*)d_in[6];
    const float* W2  = (const float*)d_in[7];
    const float* as2 = (const float*)d_in[8];
    const float* ad2 = (const float*)d_in[9];
    const float* b2  = (const float*)d_in[10];
    const float* Wk  = (const float*)d_in[11];
    const float* bk  = (const float*)d_in[12];
    const float* Wq  = (const float*)d_in[13];
    const float* bq  = (const float*)d_in[14];
    const float* Wv  = (const float*)d_in[15];
    const float* bv  = (const float*)d_in[16];
    const float* arel= (const float*)d_in[17];
    const float* mrel= (const float*)d_in[18];
    const float* prel= (const float*)d_in[19];
    const float* Wo  = (const float*)d_in[20];
    const float* bo  = (const float*)d_in[21];
    const float* skip= (const float*)d_in[22];
    const float* g1  = (const float*)d_in[23];
    const float* g2  = (const float*)d_in[24];
    const float* g3  = (const float*)d_in[25];
    const int* ei[4] = {(const int*)d_in[26], (const int*)d_in[27],
                        (const int*)d_in[28], (const int*)d_in[29]};

    float *h_, *k_, *q_, *v_, *tmp_, *al_, *ar_, *big1_, *big2_;
    int *deg_, *off_, *cur_, *csr_;
    cudaGetSymbolAddress((void**)&h_,   g_h);
    cudaGetSymbolAddress((void**)&k_,   g_k);
    cudaGetSymbolAddress((void**)&q_,   g_q);
    cudaGetSymbolAddress((void**)&v_,   g_v);
    cudaGetSymbolAddress((void**)&tmp_, g_tmp);
    cudaGetSymbolAddress((void**)&al_,  g_al);
    cudaGetSymbolAddress((void**)&ar_,  g_ar);
    cudaGetSymbolAddress((void**)&big1_,g_big1);
    cudaGetSymbolAddress((void**)&big2_,g_big2);
    cudaGetSymbolAddress((void**)&deg_, g_deg);
    cudaGetSymbolAddress((void**)&off_, g_off);
    cudaGetSymbolAddress((void**)&cur_, g_cur);
    cudaGetSymbolAddress((void**)&csr_, g_csr);

    const int nd = Nn*Dd;
    const int TPB = 256;
    const int gemm_grid = (Nn + 63) / 64;
    const int warp_grid = (Nn*32 + TPB-1) / TPB;

    add3k<<<(nd/4 + TPB-1)/TPB, TPB>>>((const float4*)zL, (const float4*)zH,
                                       (const float4*)xe, (float4*)h_, nd/4);

    // --- CSR build (once; shared by both GAT layers and HGT) ---
    zeroint<<<(TN + TPB-1)/TPB, TPB>>>(deg_, TN);
    deg_k<<<(E4 + TPB-1)/TPB, TPB>>>(ei[0], ei[1], ei[2], ei[3], deg_);
    scan_k<<<1, 1024>>>(deg_, off_, cur_);
    fill_k<<<(E4 + TPB-1)/TPB, TPB>>>(ei[0], ei[1], ei[2], ei[3], cur_, csr_);

    // --- two hetero-GAT layers ---
    const float* Ws[2]  = {W1, W2};
    const float* ass[2] = {as1, as2};
    const float* ads[2] = {ad1, ad2};
    const float* bs[2]  = {b1, b2};
    const float* gs[2]  = {g1, g2};
    for (int L = 0; L < 2; L++) {
        gemm128<true><<<dim3(gemm_grid, Tt), TPB>>>(h_, Ws[L], nullptr, big1_,
                                                    ass[L], ads[L], al_, ar_, Nn);
        gat_gather<<<warp_grid, TPB>>>(csr_, off_, deg_, al_, ar_, big1_,
                                       bs[L], gs[L], h_);
    }

    // --- HGT layer ---
    gemm128<false><<<dim3(gemm_grid,1), TPB>>>(h_, Wk, bk, k_, nullptr, nullptr, nullptr, nullptr, Nn);
    gemm128<false><<<dim3(gemm_grid,1), TPB>>>(h_, Wq, bq, q_, nullptr, nullptr, nullptr, nullptr, Nn);
    gemm128<false><<<dim3(gemm_grid,1), TPB>>>(h_, Wv, bv, v_, nullptr, nullptr, nullptr, nullptr, Nn);
    hgt_rel<true ><<<(Nn*Tt*Hh + TPB-1)/TPB, TPB>>>(q_, arel, big1_);  // qA
    hgt_rel<false><<<(Nn*Tt*Hh + TPB-1)/TPB, TPB>>>(v_, mrel, big2_);  // vM
    hgt_gather<<<warp_grid, TPB>>>(csr_, off_, deg_, k_, big1_, prel, big2_, tmp_);
    gemm128<false><<<dim3(gemm_grid,1), TPB>>>(tmp_, Wo, bo, k_, nullptr, nullptr, nullptr, nullptr, Nn);
    hgt_post<<<Nn, Dd>>>(h_, k_, g3, skip, (float*)d_out);
}

// round 6
// speedup vs baseline: 2.9661x; 2.9661x over previous
#include <cuda_runtime.h>
#include <math.h>

#define Nn 50000
#define Dd 128
#define Tt 4
#define Ee 150000
#define Hh 8
#define E4  (Tt * Ee)
#define TN  (Tt * Nn)
#define NEG_SLOPE 0.2f
#define EPSF 1e-6f
#define SCAN_NB ((TN + 1023) / 1024)

// ---------------- scratch (static device globals; no allocation) ----------------
__device__ float g_h[Nn*Dd];
__device__ float g_k[Nn*Dd];
__device__ float g_q[Nn*Dd];
__device__ float g_v[Nn*Dd];
__device__ float g_tmp[Nn*Dd];
__device__ float g_al[TN*Hh];
__device__ float g_ar[TN*Hh];
__device__ float g_xw[(size_t)Tt*Nn*Dd];    // GAT per-type transformed features
__device__ int   g_deg[TN];
__device__ int   g_off[TN];
__device__ int   g_cur[TN];
__device__ int   g_csr[E4];
__device__ int   g_bsum[SCAN_NB];

// ---------------- device helpers ----------------
__device__ __forceinline__ float geluf(float x) {
    return 0.5f * x * (1.0f + erff(x * 0.7071067811865476f));
}
__device__ __forceinline__ const int* pick_ei(int t, const int* e0, const int* e1,
                                              const int* e2, const int* e3) {
    return (t == 0) ? e0 : (t == 1) ? e1 : (t == 2) ? e2 : e3;
}
__device__ __forceinline__ float dot4(float4 a, float4 b) {
    return a.x*b.x + a.y*b.y + a.z*b.z + a.w*b.w;
}
__device__ __forceinline__ float4 shfl4(float4 v, int src) {
    float4 r;
    r.x = __shfl_sync(0xffffffffu, v.x, src);
    r.y = __shfl_sync(0xffffffffu, v.y, src);
    r.z = __shfl_sync(0xffffffffu, v.z, src);
    r.w = __shfl_sync(0xffffffffu, v.w, src);
    return r;
}

// ---------------- elementwise ----------------
__global__ void add3k(const float4* __restrict__ a, const float4* __restrict__ b,
                      const float4* __restrict__ c, float4* __restrict__ o, int n4) {
    int i = blockIdx.x*blockDim.x + threadIdx.x;
    if (i < n4) {
        float4 x = a[i], y = b[i], z = c[i];
        o[i] = make_float4(x.x+y.x+z.x, x.y+y.y+z.y, x.z+y.z+z.z, x.w+y.w+z.w);
    }
}
__global__ void zeroint(int* __restrict__ p, int n) {
    int i = blockIdx.x*blockDim.x + threadIdx.x;
    if (i < n) p[i] = 0;
}

// ---------------- CSR build (edge index is launch-invariant) ----------------
__global__ void deg_k(const int* __restrict__ e0, const int* __restrict__ e1,
                      const int* __restrict__ e2, const int* __restrict__ e3,
                      int* __restrict__ deg) {
    int idx = blockIdx.x*blockDim.x + threadIdx.x;
    if (idx >= E4) return;
    int t = idx / Ee, e = idx - t*Ee;
    const int* ei = pick_ei(t, e0, e1, e2, e3);
    atomicAdd(&deg[t*Nn + ei[Ee + e]], 1);
}

// 3-phase parallel exclusive scan over TN ints
__global__ void scan_pre(const int* __restrict__ deg, int* __restrict__ bsum) {
    __shared__ int sh[32];
    int g = blockIdx.x*1024 + threadIdx.x;
    int v = (g < TN) ? deg[g] : 0;
    int lane = threadIdx.x & 31, w = threadIdx.x >> 5;
    #pragma unroll
    for (int o = 16; o > 0; o >>= 1) v += __shfl_xor_sync(~0u, v, o);
    if (lane == 0) sh[w] = v;
    __syncthreads();
    if (w == 0) {
        int s = sh[lane];
        #pragma unroll
        for (int o = 16; o > 0; o >>= 1) s += __shfl_xor_sync(~0u, s, o);
        if (lane == 0) bsum[blockIdx.x] = s;
    }
}
__global__ void scan_mid(int* __restrict__ bsum) {   // 1 block, 256 threads, NB<=256
    __shared__ int ws[8];
    int tid = threadIdx.x;
    int v = (tid < SCAN_NB) ? bsum[tid] : 0;
    int lane = tid & 31, w = tid >> 5;
    int x = v;
    #pragma unroll
    for (int o = 1; o < 32; o <<= 1) { int u = __shfl_up_sync(~0u, x, o); if (lane >= o) x += u; }
    if (lane == 31) ws[w] = x;
    __syncthreads();
    if (w == 0 && lane < 8) {
        int y = ws[lane];
        #pragma unroll
        for (int o = 1; o < 8; o <<= 1) { int u = __shfl_up_sync(0xffu, y, o); if (lane >= o) y += u; }
        ws[lane] = y;
    }
    __syncthreads();
    int excl = x - v + (w > 0 ? ws[w-1] : 0);
    if (tid < SCAN_NB) bsum[tid] = excl;
}
__global__ void scan_post(const int* __restrict__ deg, const int* __restrict__ bsum,
                          int* __restrict__ off, int* __restrict__ cur) {
    __shared__ int ws[32];
    int g = blockIdx.x*1024 + threadIdx.x;
    int v = (g < TN) ? deg[g] : 0;
    int lane = threadIdx.x & 31, w = threadIdx.x >> 5;
    int x = v;
    #pragma unroll
    for (int o = 1; o < 32; o <<= 1) { int u = __shfl_up_sync(~0u, x, o); if (lane >= o) x += u; }
    if (lane == 31) ws[w] = x;
    __syncthreads();
    if (w == 0) {
        int y = ws[lane];
        #pragma unroll
        for (int o = 1; o < 32; o <<= 1) { int u = __shfl_up_sync(~0u, y, o); if (lane >= o) y += u; }
        ws[lane] = y;
    }
    __syncthreads();
    int excl = x - v + (w > 0 ? ws[w-1] : 0) + bsum[blockIdx.x];
    if (g < TN) { off[g] = excl; cur[g] = excl; }
}
__global__ void fill_k(const int* __restrict__ e0, const int* __restrict__ e1,
                       const int* __restrict__ e2, const int* __restrict__ e3,
                       int* __restrict__ cur, int* __restrict__ csr) {
    int idx = blockIdx.x*blockDim.x + threadIdx.x;
    if (idx >= E4) return;
    int t = idx / Ee, e = idx - t*Ee;
    const int* ei = pick_ei(t, e0, e1, e2, e3);
    int src = ei[e], dst = ei[Ee + e];
    int slot = atomicAdd(&cur[t*Nn + dst], 1);
    csr[slot] = src;
}

// ---------------- GEMM: C[Mx128] = A[Mx128] @ W[128x128] (+ bias) ----------------
// gridDim.y selects weight matrix t. If ALAR: also emit al/ar attention scalars.
template <bool ALAR>
__global__ void gemm128(const float* __restrict__ A, const float* __restrict__ Wbase,
                        const float* __restrict__ bias, float* __restrict__ Cbase,
                        const float* __restrict__ asb, const float* __restrict__ adb,
                        float* __restrict__ al, float* __restrict__ ar, int M) {
    __shared__ float As[64][128];
    const int t = blockIdx.y;
    const float* W = Wbase + (size_t)t*Dd*Dd;
    float* C = Cbase + (size_t)t*M*Dd;
    const int block_row = blockIdx.x * 64;
    const int tid = threadIdx.x;
    for (int i = tid; i < 64*32; i += 256) {
        int r = i >> 5, c4 = i & 31;
        int gr = block_row + r;
        float4 val = (gr < M) ? *(const float4*)(A + (size_t)gr*Dd + c4*4) : make_float4(0,0,0,0);
        *(float4*)(&As[r][c4*4]) = val;
    }
    __syncthreads();
    const int tx = tid & 31, ty = tid >> 5;
    const int c = tx * 4;
    float4 acc[8];
    #pragma unroll
    for (int i = 0; i < 8; i++) acc[i] = make_float4(0,0,0,0);
    #pragma unroll 4
    for (int k = 0; k < 128; k++) {
        float4 w = *(const float4*)(W + k*Dd + c);
        #pragma unroll
        for (int i = 0; i < 8; i++) {
            float a = As[ty*8 + i][k];
            acc[i].x += a*w.x; acc[i].y += a*w.y; acc[i].z += a*w.z; acc[i].w += a*w.w;
        }
    }
    float4 b4 = bias ? *(const float4*)(bias + c) : make_float4(0,0,0,0);
    #pragma unroll
    for (int i = 0; i < 8; i++) {
        int gr = block_row + ty*8 + i;
        if (gr < M) {
            float4 o = acc[i];
            o.x += b4.x; o.y += b4.y; o.z += b4.z; o.w += b4.w;
            *(float4*)(C + (size_t)gr*Dd + c) = o;
        }
    }
    if (ALAR) {
        float4 s4 = *(const float4*)(asb + t*Dd + c);
        float4 d4 = *(const float4*)(adb + t*Dd + c);
        #pragma unroll
        for (int i = 0; i < 8; i++) {
            float pa = acc[i].x*s4.x + acc[i].y*s4.y + acc[i].z*s4.z + acc[i].w*s4.w;
            float pr = acc[i].x*d4.x + acc[i].y*d4.y + acc[i].z*d4.z + acc[i].w*d4.w;
            pa += __shfl_xor_sync(0xffffffffu, pa, 1);
            pa += __shfl_xor_sync(0xffffffffu, pa, 2);
            pr += __shfl_xor_sync(0xffffffffu, pr, 1);
            pr += __shfl_xor_sync(0xffffffffu, pr, 2);
            int gr = block_row + ty*8 + i;
            if (gr < M && (tx & 3) == 0) {
                int o = ((t*Nn) + gr)*Hh + (tx >> 2);
                al[o] = pa;
                ar[o] = pr;
            }
        }
    }
}

// ---------------- GAT gather over xw (one warp per dst; fuses softmax-normalize,
// per-type sum, bias, rmsnorm residual, gelu). No atomics. ----------------
__global__ void gat_gather(const int* __restrict__ csr, const int* __restrict__ off,
                           const int* __restrict__ deg, const float* __restrict__ al,
                           const float* __restrict__ ar, const float* __restrict__ xw,
                           const float* __restrict__ b, const float* __restrict__ g,
                           float* __restrict__ h) {
    int gt = blockIdx.x*blockDim.x + threadIdx.x;
    int n = gt >> 5, lane = gt & 31;
    if (n >= Nn) return;
    int hh = lane >> 2;

    float4 a4;
    {
        float4 b0 = *(const float4*)(b + lane*4);
        float4 b1 = *(const float4*)(b + Dd + lane*4);
        float4 b2 = *(const float4*)(b + 2*Dd + lane*4);
        float4 b3 = *(const float4*)(b + 3*Dd + lane*4);
        a4 = make_float4(b0.x+b1.x+b2.x+b3.x, b0.y+b1.y+b2.y+b3.y,
                         b0.z+b1.z+b2.z+b3.z, b0.w+b1.w+b2.w+b3.w);
    }

    #pragma unroll
    for (int t = 0; t < Tt; t++) {
        int i = t*Nn + n;
        float arn = ar[(size_t)i*Hh + hh];
        // self loop (src = dst = n)
        float v = al[(size_t)i*Hh + hh] + arn;
        v = v > 0.f ? v : NEG_SLOPE*v;
        float p = expf(v);
        float s = p;
        float4 x = *(const float4*)(xw + (size_t)i*Dd + lane*4);
        float4 f = make_float4(x.x*p, x.y*p, x.z*p, x.w*p);

        int st = off[i], dg = deg[i];
        for (int j0 = 0; j0 < dg; j0 += 32) {
            int myS = (j0 + lane < dg) ? csr[st + j0 + lane] : 0;
            int cnt = min(32, dg - j0);
            for (int j = 0; j < cnt; j++) {
                int src = __shfl_sync(0xffffffffu, myS, j);
                float vv = al[((size_t)t*Nn + src)*Hh + hh] + arn;
                vv = vv > 0.f ? vv : NEG_SLOPE*vv;
                float pp = expf(vv);
                s += pp;
                float4 xx = *(const float4*)(xw + ((size_t)t*Nn + src)*Dd + lane*4);
                f.x += xx.x*pp; f.y += xx.y*pp; f.z += xx.z*pp; f.w += xx.w*pp;
            }
        }
        float inv = 1.f / s;   // s >= exp(self) > 0
        a4.x += f.x*inv; a4.y += f.y*inv; a4.z += f.z*inv; a4.w += f.w*inv;
    }

    // rmsnorm(a4, g) + residual gelu, warp-wide over 128 dims
    float ss = a4.x*a4.x + a4.y*a4.y + a4.z*a4.z + a4.w*a4.w;
    #pragma unroll
    for (int o = 16; o > 0; o >>= 1) ss += __shfl_xor_sync(0xffffffffu, ss, o);
    float inv = rsqrtf(ss * (1.0f/Dd) + EPSF);
    float4 g4 = *(const float4*)(g + lane*4);
    float4 h4 = *(const float4*)(h + (size_t)n*Dd + lane*4);
    float4 o4;
    o4.x = geluf(h4.x + g4.x*a4.x*inv);
    o4.y = geluf(h4.y + g4.y*a4.y*inv);
    o4.z = geluf(h4.z + g4.z*a4.z*inv);
    o4.w = geluf(h4.w + g4.w*a4.w*inv);
    *(float4*)(h + (size_t)n*Dd + lane*4) = o4;
}

// ---------------- HGT gather: qA in regs, mrel applied to reg accumulator ------
// Valid: arel/mrel are per-head 16x16 blocks, same head as alpha.
__global__ void hgt_gather2(const int* __restrict__ csr, const int* __restrict__ off,
                            const int* __restrict__ deg, const float* __restrict__ k,
                            const float* __restrict__ q, const float* __restrict__ v,
                            const float* __restrict__ arel, const float* __restrict__ mrel,
                            const float* __restrict__ prel, float* __restrict__ out) {
    int gt = blockIdx.x*blockDim.x + threadIdx.x;
    int n = gt >> 5, lane = gt & 31;
    if (n >= Nn) return;
    int hh = lane >> 2, qd = lane & 3;
    int qbase = lane & ~3;

    float4 qv = *(const float4*)(q + (size_t)n*Dd + lane*4);
    float4 acc = make_float4(0,0,0,0);
    float s = 0.f;

    #pragma unroll
    for (int t = 0; t < Tt; t++) {
        // qA_d = sum_f arel[t][hh][d][f] * q_f   (my d = qd*4 .. qd*4+3)
        const float* A = arel + (size_t)((t*Hh + hh)*16)*16;
        float4 qA = make_float4(0,0,0,0);
        #pragma unroll
        for (int fq = 0; fq < 4; fq++) {
            float4 qb = shfl4(qv, qbase | fq);
            #pragma unroll
            for (int i = 0; i < 4; i++) {
                float4 a4 = *(const float4*)(A + (qd*4 + i)*16 + fq*4);
                float val = dot4(a4, qb);
                if (i == 0) qA.x += val;
                else if (i == 1) qA.y += val;
                else if (i == 2) qA.z += val;
                else qA.w += val;
            }
        }
        float pr = prel[t*Hh + hh] * 0.25f;   // / sqrt(16)

        float4 aggv = make_float4(0,0,0,0);
        int i0 = t*Nn + n, st = off[i0], dg = deg[i0];
        for (int j0 = 0; j0 < dg; j0 += 32) {
            int myS = (j0 + lane < dg) ? csr[st + j0 + lane] : 0;
            int cnt = min(32, dg - j0);
            for (int j = 0; j < cnt; j++) {
                int src = __shfl_sync(0xffffffffu, myS, j);
                float4 kv = *(const float4*)(k + (size_t)src*Dd + lane*4);
                float part = dot4(kv, qA);
                part += __shfl_xor_sync(0xffffffffu, part, 1);
                part += __shfl_xor_sync(0xffffffffu, part, 2);
                float p = expf(part * pr);
                s += p;
                float4 vv = *(const float4*)(v + (size_t)src*Dd + lane*4);
                aggv.x += vv.x*p; aggv.y += vv.y*p; aggv.z += vv.z*p; aggv.w += vv.w*p;
            }
        }
        // acc_f += sum_d aggv_d * mrel[t][hh][d][f]   (my f = qd*4 .. qd*4+3)
        const float* M = mrel + (size_t)((t*Hh + hh)*16)*16;
        #pragma unroll
        for (int dq = 0; dq < 4; dq++) {
            float4 ab = shfl4(aggv, qbase | dq);
            float av[4] = {ab.x, ab.y, ab.z, ab.w};
            #pragma unroll
            for (int j = 0; j < 4; j++) {
                float4 m4 = *(const float4*)(M + (dq*4 + j)*16 + qd*4);
                float aj = av[j];
                acc.x += aj*m4.x; acc.y += aj*m4.y; acc.z += aj*m4.z; acc.w += aj*m4.w;
            }
        }
    }
    float inv = 1.f / (s > 0.f ? s : 1.f);
    float4 o4;
    o4.x = geluf(acc.x*inv);
    o4.y = geluf(acc.y*inv);
    o4.z = geluf(acc.z*inv);
    o4.w = geluf(acc.w*inv);
    *(float4*)(out + (size_t)n*Dd + lane*4) = o4;
}

// out = gelu(h + rmsnorm(beta*o + (1-beta)*h, g)),  beta = sigmoid(skip)
__global__ void hgt_post(const float* __restrict__ h, const float* __restrict__ o,
                         const float* __restrict__ g, const float* __restrict__ skip,
                         float* __restrict__ out) {
    int n = blockIdx.x, d = threadIdx.x;
    float beta = 1.f / (1.f + expf(-skip[0]));
    int i = n*Dd + d;
    float hv = h[i];
    float u = beta*o[i] + (1.f - beta)*hv;
    float ss = u*u;
    #pragma unroll
    for (int off = 16; off > 0; off >>= 1) ss += __shfl_xor_sync(0xffffffffu, ss, off);
    __shared__ float sw[4];
    if ((d & 31) == 0) sw[d >> 5] = ss;
    __syncthreads();
    float tot = sw[0] + sw[1] + sw[2] + sw[3];
    float y = g[d] * u * rsqrtf(tot * (1.0f/Dd) + EPSF);
    out[i] = geluf(hv + y);
}

// ---------------- host launch ----------------
extern "C" void kernel_launch(void* const* d_in, const int* in_sizes, int n_in,
                              void* d_out, int out_size) {
    const float* zL  = (const float*)d_in[0];
    const float* zH  = (const float*)d_in[1];
    const float* xe  = (const float*)d_in[2];
    const float* W1  = (const float*)d_in[3];
    const float* as1 = (const float*)d_in[4];
    const float* ad1 = (const float*)d_in[5];
    const float* b1  = (const float*)d_in[6];
    const float* W2  = (const float*)d_in[7];
    const float* as2 = (const float*)d_in[8];
    const float* ad2 = (const float*)d_in[9];
    const float* b2  = (const float*)d_in[10];
    const float* Wk  = (const float*)d_in[11];
    const float* bk  = (const float*)d_in[12];
    const float* Wq  = (const float*)d_in[13];
    const float* bq  = (const float*)d_in[14];
    const float* Wv  = (const float*)d_in[15];
    const float* bv  = (const float*)d_in[16];
    const float* arel= (const float*)d_in[17];
    const float* mrel= (const float*)d_in[18];
    const float* prel= (const float*)d_in[19];
    const float* Wo  = (const float*)d_in[20];
    const float* bo  = (const float*)d_in[21];
    const float* skip= (const float*)d_in[22];
    const float* g1  = (const float*)d_in[23];
    const float* g2  = (const float*)d_in[24];
    const float* g3  = (const float*)d_in[25];
    const int* ei[4] = {(const int*)d_in[26], (const int*)d_in[27],
                        (const int*)d_in[28], (const int*)d_in[29]};

    float *h_, *k_, *q_, *v_, *tmp_, *al_, *ar_, *xw_;
    int *deg_, *off_, *cur_, *csr_, *bsum_;
    cudaGetSymbolAddress((void**)&h_,   g_h);
    cudaGetSymbolAddress((void**)&k_,   g_k);
    cudaGetSymbolAddress((void**)&q_,   g_q);
    cudaGetSymbolAddress((void**)&v_,   g_v);
    cudaGetSymbolAddress((void**)&tmp_, g_tmp);
    cudaGetSymbolAddress((void**)&al_,  g_al);
    cudaGetSymbolAddress((void**)&ar_,  g_ar);
    cudaGetSymbolAddress((void**)&xw_,  g_xw);
    cudaGetSymbolAddress((void**)&deg_, g_deg);
    cudaGetSymbolAddress((void**)&off_, g_off);
    cudaGetSymbolAddress((void**)&cur_, g_cur);
    cudaGetSymbolAddress((void**)&csr_, g_csr);
    cudaGetSymbolAddress((void**)&bsum_,g_bsum);

    const int nd = Nn*Dd;
    const int TPB = 256;
    const int gemm_grid = (Nn + 63) / 64;
    const int warp_grid = (Nn*32 + TPB-1) / TPB;

    add3k<<<(nd/4 + TPB-1)/TPB, TPB>>>((const float4*)zL, (const float4*)zH,
                                       (const float4*)xe, (float4*)h_, nd/4);

    // --- CSR build (shared by GAT layers and HGT) ---
    zeroint<<<(TN + TPB-1)/TPB, TPB>>>(deg_, TN);
    deg_k<<<(E4 + TPB-1)/TPB, TPB>>>(ei[0], ei[1], ei[2], ei[3], deg_);
    scan_pre<<<SCAN_NB, 1024>>>(deg_, bsum_);
    scan_mid<<<1, 256>>>(bsum_);
    scan_post<<<SCAN_NB, 1024>>>(deg_, bsum_, off_, cur_);
    fill_k<<<(E4 + TPB-1)/TPB, TPB>>>(ei[0], ei[1], ei[2], ei[3], cur_, csr_);

    // --- two hetero-GAT layers ---
    const float* Ws[2]  = {W1, W2};
    const float* ass[2] = {as1, as2};
    const float* ads[2] = {ad1, ad2};
    const float* bs[2]  = {b1, b2};
    const float* gs[2]  = {g1, g2};
    for (int L = 0; L < 2; L++) {
        gemm128<true><<<dim3(gemm_grid, Tt), TPB>>>(h_, Ws[L], nullptr, xw_,
                                                    ass[L], ads[L], al_, ar_, Nn);
        gat_gather<<<warp_grid, TPB>>>(csr_, off_, deg_, al_, ar_, xw_,
                                       bs[L], gs[L], h_);
    }

    // --- HGT layer ---
    gemm128<false><<<dim3(gemm_grid,1), TPB>>>(h_, Wk, bk, k_, nullptr, nullptr, nullptr, nullptr, Nn);
    gemm128<false><<<dim3(gemm_grid,1), TPB>>>(h_, Wq, bq, q_, nullptr, nullptr, nullptr, nullptr, Nn);
    gemm128<false><<<dim3(gemm_grid,1), TPB>>>(h_, Wv, bv, v_, nullptr, nullptr, nullptr, nullptr, Nn);
    hgt_gather2<<<warp_grid, TPB>>>(csr_, off_, deg_, k_, q_, v_, arel, mrel, prel, tmp_);
    gemm128<false><<<dim3(gemm_grid,1), TPB>>>(tmp_, Wo, bo, k_, nullptr, nullptr, nullptr, nullptr, Nn);
    hgt_post<<<Nn, Dd>>>(h_, k_, g3, skip, (float*)d_out);
}

// round 7
// speedup vs baseline: 3.1988x; 1.0784x over previous
#include <cuda_runtime.h>
#include <math.h>

#define Nn 50000
#define Dd 128
#define Tt 4
#define Ee 150000
#define Hh 8
#define E4  (Tt * Ee)
#define TN  (Tt * Nn)
#define NEG_SLOPE 0.2f
#define EPSF 1e-6f
#define SCAN_NB ((TN + 1023) / 1024)

// ---------------- scratch (static device globals; no allocation) ----------------
__device__ float g_h[Nn*Dd];
__device__ float g_k[Nn*Dd];
__device__ float g_q[Nn*Dd];
__device__ float g_v[Nn*Dd];
__device__ float g_tmp[Nn*Dd];
__device__ float g_al[TN*Hh];
__device__ float g_ar[TN*Hh];
__device__ float g_xw[(size_t)Tt*Nn*Dd];    // GAT per-type transformed features
__device__ int   g_deg[TN];
__device__ int   g_off[TN];
__device__ int   g_cur[TN];
__device__ int   g_csr[E4];
__device__ int   g_bsum[SCAN_NB];

// ---------------- device helpers ----------------
__device__ __forceinline__ float geluf(float x) {
    return 0.5f * x * (1.0f + erff(x * 0.7071067811865476f));
}
__device__ __forceinline__ const int* pick_ei(int t, const int* e0, const int* e1,
                                              const int* e2, const int* e3) {
    return (t == 0) ? e0 : (t == 1) ? e1 : (t == 2) ? e2 : e3;
}
__device__ __forceinline__ float dot4(float4 a, float4 b) {
    return a.x*b.x + a.y*b.y + a.z*b.z + a.w*b.w;
}
__device__ __forceinline__ float4 shfl4(float4 v, int src) {
    float4 r;
    r.x = __shfl_sync(0xffffffffu, v.x, src);
    r.y = __shfl_sync(0xffffffffu, v.y, src);
    r.z = __shfl_sync(0xffffffffu, v.z, src);
    r.w = __shfl_sync(0xffffffffu, v.w, src);
    return r;
}

// ---------------- elementwise ----------------
__global__ void add3k(const float4* __restrict__ a, const float4* __restrict__ b,
                      const float4* __restrict__ c, float4* __restrict__ o, int n4) {
    int i = blockIdx.x*blockDim.x + threadIdx.x;
    if (i < n4) {
        float4 x = a[i], y = b[i], z = c[i];
        o[i] = make_float4(x.x+y.x+z.x, x.y+y.y+z.y, x.z+y.z+z.z, x.w+y.w+z.w);
    }
}
__global__ void zeroint(int* __restrict__ p, int n) {
    int i = blockIdx.x*blockDim.x + threadIdx.x;
    if (i < n) p[i] = 0;
}

// ---------------- CSR build (edge index is launch-invariant) ----------------
__global__ void deg_k(const int* __restrict__ e0, const int* __restrict__ e1,
                      const int* __restrict__ e2, const int* __restrict__ e3,
                      int* __restrict__ deg) {
    int idx = blockIdx.x*blockDim.x + threadIdx.x;
    if (idx >= E4) return;
    int t = idx / Ee, e = idx - t*Ee;
    const int* ei = pick_ei(t, e0, e1, e2, e3);
    atomicAdd(&deg[t*Nn + ei[Ee + e]], 1);
}

// 3-phase parallel exclusive scan over TN ints
__global__ void scan_pre(const int* __restrict__ deg, int* __restrict__ bsum) {
    __shared__ int sh[32];
    int g = blockIdx.x*1024 + threadIdx.x;
    int v = (g < TN) ? deg[g] : 0;
    int lane = threadIdx.x & 31, w = threadIdx.x >> 5;
    #pragma unroll
    for (int o = 16; o > 0; o >>= 1) v += __shfl_xor_sync(~0u, v, o);
    if (lane == 0) sh[w] = v;
    __syncthreads();
    if (w == 0) {
        int s = sh[lane];
        #pragma unroll
        for (int o = 16; o > 0; o >>= 1) s += __shfl_xor_sync(~0u, s, o);
        if (lane == 0) bsum[blockIdx.x] = s;
    }
}
__global__ void scan_mid(int* __restrict__ bsum) {   // 1 block, 256 threads, NB<=256
    __shared__ int ws[8];
    int tid = threadIdx.x;
    int v = (tid < SCAN_NB) ? bsum[tid] : 0;
    int lane = tid & 31, w = tid >> 5;
    int x = v;
    #pragma unroll
    for (int o = 1; o < 32; o <<= 1) { int u = __shfl_up_sync(~0u, x, o); if (lane >= o) x += u; }
    if (lane == 31) ws[w] = x;
    __syncthreads();
    if (w == 0 && lane < 8) {
        int y = ws[lane];
        #pragma unroll
        for (int o = 1; o < 8; o <<= 1) { int u = __shfl_up_sync(0xffu, y, o); if (lane >= o) y += u; }
        ws[lane] = y;
    }
    __syncthreads();
    int excl = x - v + (w > 0 ? ws[w-1] : 0);
    if (tid < SCAN_NB) bsum[tid] = excl;
}
__global__ void scan_post(const int* __restrict__ deg, const int* __restrict__ bsum,
                          int* __restrict__ off, int* __restrict__ cur) {
    __shared__ int ws[32];
    int g = blockIdx.x*1024 + threadIdx.x;
    int v = (g < TN) ? deg[g] : 0;
    int lane = threadIdx.x & 31, w = threadIdx.x >> 5;
    int x = v;
    #pragma unroll
    for (int o = 1; o < 32; o <<= 1) { int u = __shfl_up_sync(~0u, x, o); if (lane >= o) x += u; }
    if (lane == 31) ws[w] = x;
    __syncthreads();
    if (w == 0) {
        int y = ws[lane];
        #pragma unroll
        for (int o = 1; o < 32; o <<= 1) { int u = __shfl_up_sync(~0u, y, o); if (lane >= o) y += u; }
        ws[lane] = y;
    }
    __syncthreads();
    int excl = x - v + (w > 0 ? ws[w-1] : 0) + bsum[blockIdx.x];
    if (g < TN) { off[g] = excl; cur[g] = excl; }
}
__global__ void fill_k(const int* __restrict__ e0, const int* __restrict__ e1,
                       const int* __restrict__ e2, const int* __restrict__ e3,
                       int* __restrict__ cur, int* __restrict__ csr) {
    int idx = blockIdx.x*blockDim.x + threadIdx.x;
    if (idx >= E4) return;
    int t = idx / Ee, e = idx - t*Ee;
    const int* ei = pick_ei(t, e0, e1, e2, e3);
    int src = ei[e], dst = ei[Ee + e];
    int slot = atomicAdd(&cur[t*Nn + dst], 1);
    csr[slot] = src;
}

// ---------------- GEMM: C[Mx128] = A[Mx128] @ W[128x128] (+ bias) ----------------
// 128x128 block tile, 256 threads, 8x8 per thread (rows ty*8..+7, cols tx*4 & 64+tx*4).
// gridDim.y selects weight matrix t. If ALAR: also emit al/ar attention scalars.
template <bool ALAR>
__global__ void __launch_bounds__(256)
gemm_ff(const float* __restrict__ A, const float* __restrict__ Wbase,
        const float* __restrict__ bias, float* __restrict__ Cbase,
        const float* __restrict__ asb, const float* __restrict__ adb,
        float* __restrict__ al, float* __restrict__ ar, int M) {
    __shared__ float As[16][128];   // transposed: As[k][m]
    __shared__ float Ws[16][128];   // Ws[k][n]
    const int t = blockIdx.y;
    const float* W = Wbase + (size_t)t*Dd*Dd;
    float* C = Cbase + (size_t)t*M*Dd;
    const int br = blockIdx.x * 128;
    const int tid = threadIdx.x;
    const int tx = tid & 15, ty = tid >> 4;

    float acc[8][8];
    #pragma unroll
    for (int i = 0; i < 8; i++)
        #pragma unroll
        for (int j = 0; j < 8; j++) acc[i][j] = 0.f;

    for (int kc = 0; kc < 8; kc++) {
        __syncthreads();
        // stage A chunk (rows br..br+127, k = kc*16..+15), transposed
        #pragma unroll
        for (int j = 0; j < 2; j++) {
            int idx = tid + j*256;          // 0..511
            int r = idx & 127, kq = idx >> 7;   // kq 0..3
            int gr = br + r;
            float4 av = (gr < M) ? *(const float4*)(A + (size_t)gr*Dd + kc*16 + kq*4)
                                 : make_float4(0,0,0,0);
            As[kq*4+0][r] = av.x;
            As[kq*4+1][r] = av.y;
            As[kq*4+2][r] = av.z;
            As[kq*4+3][r] = av.w;
        }
        // stage W chunk
        #pragma unroll
        for (int j = 0; j < 2; j++) {
            int idx = tid + j*256;          // 0..511
            int k = idx >> 5, nq = idx & 31;
            *(float4*)(&Ws[k][nq*4]) = *(const float4*)(W + (size_t)(kc*16 + k)*Dd + nq*4);
        }
        __syncthreads();
        #pragma unroll
        for (int k = 0; k < 16; k++) {
            float4 a0 = *(const float4*)(&As[k][ty*8]);
            float4 a1 = *(const float4*)(&As[k][ty*8+4]);
            float4 b0 = *(const float4*)(&Ws[k][tx*4]);
            float4 b1 = *(const float4*)(&Ws[k][64 + tx*4]);
            float av[8] = {a0.x,a0.y,a0.z,a0.w,a1.x,a1.y,a1.z,a1.w};
            float bv[8] = {b0.x,b0.y,b0.z,b0.w,b1.x,b1.y,b1.z,b1.w};
            #pragma unroll
            for (int i = 0; i < 8; i++)
                #pragma unroll
                for (int j = 0; j < 8; j++)
                    acc[i][j] += av[i]*bv[j];
        }
    }

    // epilogue: bias + store; optional al/ar head dots
    float4 bb0 = make_float4(0,0,0,0), bb1 = make_float4(0,0,0,0);
    if (bias) {
        bb0 = *(const float4*)(bias + tx*4);
        bb1 = *(const float4*)(bias + 64 + tx*4);
    }
    float4 s0, s1, d0, d1;
    if (ALAR) {
        s0 = *(const float4*)(asb + t*Dd + tx*4);
        s1 = *(const float4*)(asb + t*Dd + 64 + tx*4);
        d0 = *(const float4*)(adb + t*Dd + tx*4);
        d1 = *(const float4*)(adb + t*Dd + 64 + tx*4);
    }
    #pragma unroll
    for (int i = 0; i < 8; i++) {
        int gr = br + ty*8 + i;
        float4 o0 = make_float4(acc[i][0]+bb0.x, acc[i][1]+bb0.y,
                                acc[i][2]+bb0.z, acc[i][3]+bb0.w);
        float4 o1 = make_float4(acc[i][4]+bb1.x, acc[i][5]+bb1.y,
                                acc[i][6]+bb1.z, acc[i][7]+bb1.w);
        if (gr < M) {
            *(float4*)(C + (size_t)gr*Dd + tx*4) = o0;
            *(float4*)(C + (size_t)gr*Dd + 64 + tx*4) = o1;
        }
        if (ALAR) {
            // head dots over 16 cols = quad of tx (reduce via xor 1,2 within warp)
            float pa0 = acc[i][0]*s0.x + acc[i][1]*s0.y + acc[i][2]*s0.z + acc[i][3]*s0.w;
            float pa1 = acc[i][4]*s1.x + acc[i][5]*s1.y + acc[i][6]*s1.z + acc[i][7]*s1.w;
            float pr0 = acc[i][0]*d0.x + acc[i][1]*d0.y + acc[i][2]*d0.z + acc[i][3]*d0.w;
            float pr1 = acc[i][4]*d1.x + acc[i][5]*d1.y + acc[i][6]*d1.z + acc[i][7]*d1.w;
            pa0 += __shfl_xor_sync(~0u, pa0, 1); pa0 += __shfl_xor_sync(~0u, pa0, 2);
            pa1 += __shfl_xor_sync(~0u, pa1, 1); pa1 += __shfl_xor_sync(~0u, pa1, 2);
            pr0 += __shfl_xor_sync(~0u, pr0, 1); pr0 += __shfl_xor_sync(~0u, pr0, 2);
            pr1 += __shfl_xor_sync(~0u, pr1, 1); pr1 += __shfl_xor_sync(~0u, pr1, 2);
            if (gr < M && (tx & 3) == 0) {
                int base = ((t*Nn) + gr)*Hh;
                int hh0 = tx >> 2, hh1 = 4 + (tx >> 2);
                al[base + hh0] = pa0;
                al[base + hh1] = pa1;
                ar[base + hh0] = pr0;
                ar[base + hh1] = pr1;
            }
        }
    }
}

// ---------------- GAT gather: one BLOCK per dst node, one warp per type. -------
// Fuses softmax-normalize, per-type sum, bias, rmsnorm residual, gelu. No atomics.
__global__ void gat_gather_b(const int* __restrict__ csr, const int* __restrict__ off,
                             const int* __restrict__ deg, const float* __restrict__ al,
                             const float* __restrict__ ar, const float* __restrict__ xw,
                             const float* __restrict__ b, const float* __restrict__ g,
                             float* __restrict__ h) {
    int n = blockIdx.x;
    int tid = threadIdx.x;
    int t = tid >> 5, lane = tid & 31;
    int hh = lane >> 2;
    __shared__ float smf[4][128];
    __shared__ float sw[4];

    {
        int i = t*Nn + n;
        float arn = ar[(size_t)i*Hh + hh];
        // self loop (src = dst = n)
        float v = al[(size_t)i*Hh + hh] + arn;
        v = v > 0.f ? v : NEG_SLOPE*v;
        float p = expf(v);
        float s = p;
        float4 x = *(const float4*)(xw + (size_t)i*Dd + lane*4);
        float4 f = make_float4(x.x*p, x.y*p, x.z*p, x.w*p);

        int st = off[i], dg = deg[i];
        for (int j0 = 0; j0 < dg; j0 += 32) {
            int myS = (j0 + lane < dg) ? csr[st + j0 + lane] : 0;
            int cnt = min(32, dg - j0);
            for (int j = 0; j < cnt; j++) {
                int src = __shfl_sync(0xffffffffu, myS, j);
                float vv = al[((size_t)t*Nn + src)*Hh + hh] + arn;
                vv = vv > 0.f ? vv : NEG_SLOPE*vv;
                float pp = expf(vv);
                s += pp;
                float4 xx = *(const float4*)(xw + ((size_t)t*Nn + src)*Dd + lane*4);
                f.x += xx.x*pp; f.y += xx.y*pp; f.z += xx.z*pp; f.w += xx.w*pp;
            }
        }
        float inv = 1.f / s;   // s >= exp(self) > 0
        *(float4*)(&smf[t][lane*4]) = make_float4(f.x*inv, f.y*inv, f.z*inv, f.w*inv);
    }
    __syncthreads();

    // combine across types with 128 threads, then rmsnorm + residual gelu
    int d = tid;
    float a = smf[0][d] + smf[1][d] + smf[2][d] + smf[3][d]
            + b[d] + b[Dd + d] + b[2*Dd + d] + b[3*Dd + d];
    float ss = a*a;
    #pragma unroll
    for (int o = 16; o > 0; o >>= 1) ss += __shfl_xor_sync(0xffffffffu, ss, o);
    if (lane == 0) sw[t] = ss;
    __syncthreads();
    float tot = sw[0] + sw[1] + sw[2] + sw[3];
    float inv2 = rsqrtf(tot * (1.0f/Dd) + EPSF);
    int i = n*Dd + d;
    h[i] = geluf(h[i] + g[d] * a * inv2);
}

// ---------------- HGT gather: one BLOCK per dst, one warp per type. ------------
// qA in regs, mrel applied per-type; unnormalized acc + s summed across warps
// (joint softmax is additive). Fuses normalize + gelu. No atomics.
__global__ void hgt_gather_b(const int* __restrict__ csr, const int* __restrict__ off,
                             const int* __restrict__ deg, const float* __restrict__ k,
                             const float* __restrict__ q, const float* __restrict__ v,
                             const float* __restrict__ arel, const float* __restrict__ mrel,
                             const float* __restrict__ prel, float* __restrict__ out) {
    int n = blockIdx.x;
    int tid = threadIdx.x;
    int t = tid >> 5, lane = tid & 31;
    int hh = lane >> 2, qd = lane & 3;
    int qbase = lane & ~3;
    __shared__ float smacc[4][128];
    __shared__ float sms[4][8];

    {
        float4 qv = *(const float4*)(q + (size_t)n*Dd + lane*4);
        // qA_d = sum_f arel[t][hh][d][f] * q_f   (my d = qd*4 .. qd*4+3)
        const float* A = arel + (size_t)((t*Hh + hh)*16)*16;
        float4 qA = make_float4(0,0,0,0);
        #pragma unroll
        for (int fq = 0; fq < 4; fq++) {
            float4 qb = shfl4(qv, qbase | fq);
            #pragma unroll
            for (int i = 0; i < 4; i++) {
                float4 a4 = *(const float4*)(A + (qd*4 + i)*16 + fq*4);
                float val = dot4(a4, qb);
                if (i == 0) qA.x += val;
                else if (i == 1) qA.y += val;
                else if (i == 2) qA.z += val;
                else qA.w += val;
            }
        }
        float pr = prel[t*Hh + hh] * 0.25f;   // / sqrt(16)

        float4 aggv = make_float4(0,0,0,0);
        float s = 0.f;
        int i0 = t*Nn + n, st = off[i0], dg = deg[i0];
        for (int j0 = 0; j0 < dg; j0 += 32) {
            int myS = (j0 + lane < dg) ? csr[st + j0 + lane] : 0;
            int cnt = min(32, dg - j0);
            for (int j = 0; j < cnt; j++) {
                int src = __shfl_sync(0xffffffffu, myS, j);
                float4 kv = *(const float4*)(k + (size_t)src*Dd + lane*4);
                float part = dot4(kv, qA);
                part += __shfl_xor_sync(0xffffffffu, part, 1);
                part += __shfl_xor_sync(0xffffffffu, part, 2);
                float p = expf(part * pr);
                s += p;
                float4 vv = *(const float4*)(v + (size_t)src*Dd + lane*4);
                aggv.x += vv.x*p; aggv.y += vv.y*p; aggv.z += vv.z*p; aggv.w += vv.w*p;
            }
        }
        // acc_f = sum_d aggv_d * mrel[t][hh][d][f]   (my f = qd*4 .. qd*4+3)
        const float* M = mrel + (size_t)((t*Hh + hh)*16)*16;
        float4 acc = make_float4(0,0,0,0);
        #pragma unroll
        for (int dq = 0; dq < 4; dq++) {
            float4 ab = shfl4(aggv, qbase | dq);
            float av[4] = {ab.x, ab.y, ab.z, ab.w};
            #pragma unroll
            for (int j = 0; j < 4; j++) {
                float4 m4 = *(const float4*)(M + (dq*4 + j)*16 + qd*4);
                float aj = av[j];
                acc.x += aj*m4.x; acc.y += aj*m4.y; acc.z += aj*m4.z; acc.w += aj*m4.w;
            }
        }
        *(float4*)(&smacc[t][lane*4]) = acc;
        if (qd == 0) sms[t][hh] = s;
    }
    __syncthreads();

    int d = tid;
    int dh = d >> 4;
    float a = smacc[0][d] + smacc[1][d] + smacc[2][d] + smacc[3][d];
    float stot = sms[0][dh] + sms[1][dh] + sms[2][dh] + sms[3][dh];
    float inv = 1.f / (stot > 0.f ? stot : 1.f);
    out[(size_t)n*Dd + d] = geluf(a * inv);
}

// out = gelu(h + rmsnorm(beta*o + (1-beta)*h, g)),  beta = sigmoid(skip)
__global__ void hgt_post(const float* __restrict__ h, const float* __restrict__ o,
                         const float* __restrict__ g, const float* __restrict__ skip,
                         float* __restrict__ out) {
    int n = blockIdx.x, d = threadIdx.x;
    float beta = 1.f / (1.f + expf(-skip[0]));
    int i = n*Dd + d;
    float hv = h[i];
    float u = beta*o[i] + (1.f - beta)*hv;
    float ss = u*u;
    #pragma unroll
    for (int off = 16; off > 0; off >>= 1) ss += __shfl_xor_sync(0xffffffffu, ss, off);
    __shared__ float sw[4];
    if ((d & 31) == 0) sw[d >> 5] = ss;
    __syncthreads();
    float tot = sw[0] + sw[1] + sw[2] + sw[3];
    float y = g[d] * u * rsqrtf(tot * (1.0f/Dd) + EPSF);
    out[i] = geluf(hv + y);
}

// ---------------- host launch ----------------
extern "C" void kernel_launch(void* const* d_in, const int* in_sizes, int n_in,
                              void* d_out, int out_size) {
    const float* zL  = (const float*)d_in[0];
    const float* zH  = (const float*)d_in[1];
    const float* xe  = (const float*)d_in[2];
    const float* W1  = (const float*)d_in[3];
    const float* as1 = (const float*)d_in[4];
    const float* ad1 = (const float*)d_in[5];
    const float* b1  = (const float*)d_in[6];
    const float* W2  = (const float*)d_in[7];
    const float* as2 = (const float*)d_in[8];
    const float* ad2 = (const float*)d_in[9];
    const float* b2  = (const float*)d_in[10];
    const float* Wk  = (const float*)d_in[11];
    const float* bk  = (const float*)d_in[12];
    const float* Wq  = (const float*)d_in[13];
    const float* bq  = (const float*)d_in[14];
    const float* Wv  = (const float*)d_in[15];
    const float* bv  = (const float*)d_in[16];
    const float* arel= (const float*)d_in[17];
    const float* mrel= (const float*)d_in[18];
    const float* prel= (const float*)d_in[19];
    const float* Wo  = (const float*)d_in[20];
    const float* bo  = (const float*)d_in[21];
    const float* skip= (const float*)d_in[22];
    const float* g1  = (const float*)d_in[23];
    const float* g2  = (const float*)d_in[24];
    const float* g3  = (const float*)d_in[25];
    const int* ei[4] = {(const int*)d_in[26], (const int*)d_in[27],
                        (const int*)d_in[28], (const int*)d_in[29]};

    float *h_, *k_, *q_, *v_, *tmp_, *al_, *ar_, *xw_;
    int *deg_, *off_, *cur_, *csr_, *bsum_;
    cudaGetSymbolAddress((void**)&h_,   g_h);
    cudaGetSymbolAddress((void**)&k_,   g_k);
    cudaGetSymbolAddress((void**)&q_,   g_q);
    cudaGetSymbolAddress((void**)&v_,   g_v);
    cudaGetSymbolAddress((void**)&tmp_, g_tmp);
    cudaGetSymbolAddress((void**)&al_,  g_al);
    cudaGetSymbolAddress((void**)&ar_,  g_ar);
    cudaGetSymbolAddress((void**)&xw_,  g_xw);
    cudaGetSymbolAddress((void**)&deg_, g_deg);
    cudaGetSymbolAddress((void**)&off_, g_off);
    cudaGetSymbolAddress((void**)&cur_, g_cur);
    cudaGetSymbolAddress((void**)&csr_, g_csr);
    cudaGetSymbolAddress((void**)&bsum_,g_bsum);

    const int nd = Nn*Dd;
    const int TPB = 256;
    const int gemm_grid = (Nn + 127) / 128;

    add3k<<<(nd/4 + TPB-1)/TPB, TPB>>>((const float4*)zL, (const float4*)zH,
                                       (const float4*)xe, (float4*)h_, nd/4);

    // --- CSR build (shared by GAT layers and HGT) ---
    zeroint<<<(TN + TPB-1)/TPB, TPB>>>(deg_, TN);
    deg_k<<<(E4 + TPB-1)/TPB, TPB>>>(ei[0], ei[1], ei[2], ei[3], deg_);
    scan_pre<<<SCAN_NB, 1024>>>(deg_, bsum_);
    scan_mid<<<1, 256>>>(bsum_);
    scan_post<<<SCAN_NB, 1024>>>(deg_, bsum_, off_, cur_);
    fill_k<<<(E4 + TPB-1)/TPB, TPB>>>(ei[0], ei[1], ei[2], ei[3], cur_, csr_);

    // --- two hetero-GAT layers ---
    const float* Ws[2]  = {W1, W2};
    const float* ass[2] = {as1, as2};
    const float* ads[2] = {ad1, ad2};
    const float* bs[2]  = {b1, b2};
    const float* gs[2]  = {g1, g2};
    for (int L = 0; L < 2; L++) {
        gemm_ff<true><<<dim3(gemm_grid, Tt), TPB>>>(h_, Ws[L], nullptr, xw_,
                                                    ass[L], ads[L], al_, ar_, Nn);
        gat_gather_b<<<Nn, 128>>>(csr_, off_, deg_, al_, ar_, xw_,
                                  bs[L], gs[L], h_);
    }

    // --- HGT layer ---
    gemm_ff<false><<<dim3(gemm_grid,1), TPB>>>(h_, Wk, bk, k_, nullptr, nullptr, nullptr, nullptr, Nn);
    gemm_ff<false><<<dim3(gemm_grid,1), TPB>>>(h_, Wq, bq, q_, nullptr, nullptr, nullptr, nullptr, Nn);
    gemm_ff<false><<<dim3(gemm_grid,1), TPB>>>(h_, Wv, bv, v_, nullptr, nullptr, nullptr, nullptr, Nn);
    hgt_gather_b<<<Nn, 128>>>(csr_, off_, deg_, k_, q_, v_, arel, mrel, prel, tmp_);
    gemm_ff<false><<<dim3(gemm_grid,1), TPB>>>(tmp_, Wo, bo, k_, nullptr, nullptr, nullptr, nullptr, Nn);
    hgt_post<<<Nn, Dd>>>(h_, k_, g3, skip, (float*)d_out);
}

// round 8
// speedup vs baseline: 3.3624x; 1.0511x over previous
#include <cuda_runtime.h>
#include <math.h>

#define Nn 50000
#define Dd 128
#define Tt 4
#define Ee 150000
#define Hh 8
#define E4  (Tt * Ee)
#define TN  (Tt * Nn)
#define NEG_SLOPE 0.2f
#define EPSF 1e-6f
#define SCAN_NB ((TN + 1023) / 1024)

typedef unsigned long long u64;

// ---------------- scratch (static device globals; no allocation) ----------------
__device__ float g_h[Nn*Dd];
__device__ float g_k[Nn*Dd];
__device__ float g_q[Nn*Dd];
__device__ float g_v[Nn*Dd];
__device__ float g_tmp[Nn*Dd];
__device__ float g_al[TN*Hh];
__device__ float g_ar[TN*Hh];
__device__ float g_xw[(size_t)Tt*Nn*Dd];    // GAT per-type transformed features
__device__ int   g_deg[TN];
__device__ int   g_off[TN];
__device__ int   g_cur[TN];
__device__ int   g_csr[E4];
__device__ int   g_bsum[SCAN_NB];

// ---------------- device helpers ----------------
__device__ __forceinline__ float geluf(float x) {
    return 0.5f * x * (1.0f + erff(x * 0.7071067811865476f));
}
__device__ __forceinline__ const int* pick_ei(int t, const int* e0, const int* e1,
                                              const int* e2, const int* e3) {
    return (t == 0) ? e0 : (t == 1) ? e1 : (t == 2) ? e2 : e3;
}
__device__ __forceinline__ float dot4(float4 a, float4 b) {
    return a.x*b.x + a.y*b.y + a.z*b.z + a.w*b.w;
}
__device__ __forceinline__ float4 shfl4(float4 v, int src) {
    float4 r;
    r.x = __shfl_sync(0xffffffffu, v.x, src);
    r.y = __shfl_sync(0xffffffffu, v.y, src);
    r.z = __shfl_sync(0xffffffffu, v.z, src);
    r.w = __shfl_sync(0xffffffffu, v.w, src);
    return r;
}
// Blackwell packed fp32 FMA (FFMA2). Bit-exact vs two scalar FFMA .rn.
__device__ __forceinline__ u64 pk2(float x) {
    u64 d; unsigned r = __float_as_uint(x);
    asm("mov.b64 %0, {%1, %1};" : "=l"(d) : "r"(r));
    return d;
}
__device__ __forceinline__ void fma2(u64& c, u64 a, u64 b) {
    asm("fma.rn.f32x2 %0, %1, %2, %3;" : "=l"(c) : "l"(a), "l"(b), "l"(c));
}
__device__ __forceinline__ void upk2(u64 d, float& lo, float& hi) {
    asm("mov.b64 {%0, %1}, %2;" : "=f"(lo), "=f"(hi) : "l"(d));
}

// ---------------- elementwise ----------------
__global__ void add3k(const float4* __restrict__ a, const float4* __restrict__ b,
                      const float4* __restrict__ c, float4* __restrict__ o, int n4) {
    int i = blockIdx.x*blockDim.x + threadIdx.x;
    if (i < n4) {
        float4 x = a[i], y = b[i], z = c[i];
        o[i] = make_float4(x.x+y.x+z.x, x.y+y.y+z.y, x.z+y.z+z.z, x.w+y.w+z.w);
    }
}
__global__ void zeroint(int* __restrict__ p, int n) {
    int i = blockIdx.x*blockDim.x + threadIdx.x;
    if (i < n) p[i] = 0;
}

// ---------------- CSR build (edge index is launch-invariant) ----------------
__global__ void deg_k(const int* __restrict__ e0, const int* __restrict__ e1,
                      const int* __restrict__ e2, const int* __restrict__ e3,
                      int* __restrict__ deg) {
    int idx = blockIdx.x*blockDim.x + threadIdx.x;
    if (idx >= E4) return;
    int t = idx / Ee, e = idx - t*Ee;
    const int* ei = pick_ei(t, e0, e1, e2, e3);
    atomicAdd(&deg[t*Nn + ei[Ee + e]], 1);
}

// 3-phase parallel exclusive scan over TN ints
__global__ void scan_pre(const int* __restrict__ deg, int* __restrict__ bsum) {
    __shared__ int sh[32];
    int g = blockIdx.x*1024 + threadIdx.x;
    int v = (g < TN) ? deg[g] : 0;
    int lane = threadIdx.x & 31, w = threadIdx.x >> 5;
    #pragma unroll
    for (int o = 16; o > 0; o >>= 1) v += __shfl_xor_sync(~0u, v, o);
    if (lane == 0) sh[w] = v;
    __syncthreads();
    if (w == 0) {
        int s = sh[lane];
        #pragma unroll
        for (int o = 16; o > 0; o >>= 1) s += __shfl_xor_sync(~0u, s, o);
        if (lane == 0) bsum[blockIdx.x] = s;
    }
}
__global__ void scan_mid(int* __restrict__ bsum) {   // 1 block, 256 threads, NB<=256
    __shared__ int ws[8];
    int tid = threadIdx.x;
    int v = (tid < SCAN_NB) ? bsum[tid] : 0;
    int lane = tid & 31, w = tid >> 5;
    int x = v;
    #pragma unroll
    for (int o = 1; o < 32; o <<= 1) { int u = __shfl_up_sync(~0u, x, o); if (lane >= o) x += u; }
    if (lane == 31) ws[w] = x;
    __syncthreads();
    if (w == 0 && lane < 8) {
        int y = ws[lane];
        #pragma unroll
        for (int o = 1; o < 8; o <<= 1) { int u = __shfl_up_sync(0xffu, y, o); if (lane >= o) y += u; }
        ws[lane] = y;
    }
    __syncthreads();
    int excl = x - v + (w > 0 ? ws[w-1] : 0);
    if (tid < SCAN_NB) bsum[tid] = excl;
}
__global__ void scan_post(const int* __restrict__ deg, const int* __restrict__ bsum,
                          int* __restrict__ off, int* __restrict__ cur) {
    __shared__ int ws[32];
    int g = blockIdx.x*1024 + threadIdx.x;
    int v = (g < TN) ? deg[g] : 0;
    int lane = threadIdx.x & 31, w = threadIdx.x >> 5;
    int x = v;
    #pragma unroll
    for (int o = 1; o < 32; o <<= 1) { int u = __shfl_up_sync(~0u, x, o); if (lane >= o) x += u; }
    if (lane == 31) ws[w] = x;
    __syncthreads();
    if (w == 0) {
        int y = ws[lane];
        #pragma unroll
        for (int o = 1; o < 32; o <<= 1) { int u = __shfl_up_sync(~0u, y, o); if (lane >= o) y += u; }
        ws[lane] = y;
    }
    __syncthreads();
    int excl = x - v + (w > 0 ? ws[w-1] : 0) + bsum[blockIdx.x];
    if (g < TN) { off[g] = excl; cur[g] = excl; }
}
__global__ void fill_k(const int* __restrict__ e0, const int* __restrict__ e1,
                       const int* __restrict__ e2, const int* __restrict__ e3,
                       int* __restrict__ cur, int* __restrict__ csr) {
    int idx = blockIdx.x*blockDim.x + threadIdx.x;
    if (idx >= E4) return;
    int t = idx / Ee, e = idx - t*Ee;
    const int* ei = pick_ei(t, e0, e1, e2, e3);
    int src = ei[e], dst = ei[Ee + e];
    int slot = atomicAdd(&cur[t*Nn + dst], 1);
    csr[slot] = src;
}

// ---------------- GEMM core macros (128x128 tile, 256 thr, 8x8/thr, f32x2) -----
// Stages A (transposed) and W chunks, accumulates into u64 acc2[8][4].
#define GEMM_STAGE_AND_MAC(Aptr, Wptr, Mval)                                        \
    for (int kc = 0; kc < 8; kc++) {                                                \
        __syncthreads();                                                            \
        _Pragma("unroll")                                                           \
        for (int j = 0; j < 2; j++) {                                               \
            int idx = tid + j*256;                                                  \
            int r = idx & 127, kq = idx >> 7;                                       \
            int gr = br + r;                                                        \
            float4 av = (gr < (Mval)) ? *(const float4*)((Aptr) + (size_t)gr*Dd + kc*16 + kq*4) \
                                      : make_float4(0,0,0,0);                       \
            As[kq*4+0][r] = av.x;                                                   \
            As[kq*4+1][r] = av.y;                                                   \
            As[kq*4+2][r] = av.z;                                                   \
            As[kq*4+3][r] = av.w;                                                   \
        }                                                                           \
        _Pragma("unroll")                                                           \
        for (int j = 0; j < 2; j++) {                                               \
            int idx = tid + j*256;                                                  \
            int k = idx >> 5, nq = idx & 31;                                        \
            *(float4*)(&Ws[k][nq*4]) = *(const float4*)((Wptr) + (size_t)(kc*16 + k)*Dd + nq*4); \
        }                                                                           \
        __syncthreads();                                                            \
        _Pragma("unroll")                                                           \
        for (int k = 0; k < 16; k++) {                                              \
            float4 a0 = *(const float4*)(&As[k][ty*8]);                             \
            float4 a1 = *(const float4*)(&As[k][ty*8+4]);                           \
            const u64* w0 = (const u64*)(&Ws[k][tx*4]);                             \
            const u64* w1 = (const u64*)(&Ws[k][64 + tx*4]);                        \
            u64 bq0 = w0[0], bq1 = w0[1], bq2 = w1[0], bq3 = w1[1];                 \
            float av[8] = {a0.x,a0.y,a0.z,a0.w,a1.x,a1.y,a1.z,a1.w};                \
            _Pragma("unroll")                                                       \
            for (int i = 0; i < 8; i++) {                                           \
                u64 ad = pk2(av[i]);                                                \
                fma2(acc2[i][0], ad, bq0);                                          \
                fma2(acc2[i][1], ad, bq1);                                          \
                fma2(acc2[i][2], ad, bq2);                                          \
                fma2(acc2[i][3], ad, bq3);                                          \
            }                                                                       \
        }                                                                           \
    }

#define GEMM_UNPACK()                                                               \
    float acc[8][8];                                                                \
    _Pragma("unroll")                                                               \
    for (int i = 0; i < 8; i++) {                                                   \
        _Pragma("unroll")                                                           \
        for (int j2 = 0; j2 < 4; j2++)                                              \
            upk2(acc2[i][j2], acc[i][j2*2], acc[i][j2*2+1]);                        \
    }

// ---------------- GEMM: C[Mx128] = A[Mx128] @ W[128x128] (+ bias) ----------------
// gridDim.y selects weight matrix t. If ALAR: also emit al/ar attention scalars.
template <bool ALAR>
__global__ void __launch_bounds__(256)
gemm_ff(const float* __restrict__ A, const float* __restrict__ Wbase,
        const float* __restrict__ bias, float* __restrict__ Cbase,
        const float* __restrict__ asb, const float* __restrict__ adb,
        float* __restrict__ al, float* __restrict__ ar, int M) {
    __shared__ float As[16][128];   // transposed: As[k][m]
    __shared__ float Ws[16][128];   // Ws[k][n]
    const int t = blockIdx.y;
    const float* W = Wbase + (size_t)t*Dd*Dd;
    float* C = Cbase + (size_t)t*M*Dd;
    const int br = blockIdx.x * 128;
    const int tid = threadIdx.x;
    const int tx = tid & 15, ty = tid >> 4;

    u64 acc2[8][4];
    #pragma unroll
    for (int i = 0; i < 8; i++)
        #pragma unroll
        for (int j = 0; j < 4; j++) acc2[i][j] = 0ull;

    GEMM_STAGE_AND_MAC(A, W, M)
    GEMM_UNPACK()

    // epilogue: bias + store; optional al/ar head dots
    float4 bb0 = make_float4(0,0,0,0), bb1 = make_float4(0,0,0,0);
    if (bias) {
        bb0 = *(const float4*)(bias + tx*4);
        bb1 = *(const float4*)(bias + 64 + tx*4);
    }
    float4 s0, s1, d0, d1;
    if (ALAR) {
        s0 = *(const float4*)(asb + t*Dd + tx*4);
        s1 = *(const float4*)(asb + t*Dd + 64 + tx*4);
        d0 = *(const float4*)(adb + t*Dd + tx*4);
        d1 = *(const float4*)(adb + t*Dd + 64 + tx*4);
    }
    #pragma unroll
    for (int i = 0; i < 8; i++) {
        int gr = br + ty*8 + i;
        float4 o0 = make_float4(acc[i][0]+bb0.x, acc[i][1]+bb0.y,
                                acc[i][2]+bb0.z, acc[i][3]+bb0.w);
        float4 o1 = make_float4(acc[i][4]+bb1.x, acc[i][5]+bb1.y,
                                acc[i][6]+bb1.z, acc[i][7]+bb1.w);
        if (gr < M) {
            *(float4*)(C + (size_t)gr*Dd + tx*4) = o0;
            *(float4*)(C + (size_t)gr*Dd + 64 + tx*4) = o1;
        }
        if (ALAR) {
            float pa0 = acc[i][0]*s0.x + acc[i][1]*s0.y + acc[i][2]*s0.z + acc[i][3]*s0.w;
            float pa1 = acc[i][4]*s1.x + acc[i][5]*s1.y + acc[i][6]*s1.z + acc[i][7]*s1.w;
            float pr0 = acc[i][0]*d0.x + acc[i][1]*d0.y + acc[i][2]*d0.z + acc[i][3]*d0.w;
            float pr1 = acc[i][4]*d1.x + acc[i][5]*d1.y + acc[i][6]*d1.z + acc[i][7]*d1.w;
            pa0 += __shfl_xor_sync(~0u, pa0, 1); pa0 += __shfl_xor_sync(~0u, pa0, 2);
            pa1 += __shfl_xor_sync(~0u, pa1, 1); pa1 += __shfl_xor_sync(~0u, pa1, 2);
            pr0 += __shfl_xor_sync(~0u, pr0, 1); pr0 += __shfl_xor_sync(~0u, pr0, 2);
            pr1 += __shfl_xor_sync(~0u, pr1, 1); pr1 += __shfl_xor_sync(~0u, pr1, 2);
            if (gr < M && (tx & 3) == 0) {
                int base = ((t*Nn) + gr)*Hh;
                int hh0 = tx >> 2, hh1 = 4 + (tx >> 2);
                al[base + hh0] = pa0;
                al[base + hh1] = pa1;
                ar[base + hh0] = pr0;
                ar[base + hh1] = pr1;
            }
        }
    }
}

// ---------------- Final GEMM + HGT post fused:
// out = gelu(h + rmsnorm(beta*(A@Wo+bo) + (1-beta)*h, g)), beta = sigmoid(skip)
__global__ void __launch_bounds__(256)
gemm_wo_post(const float* __restrict__ A, const float* __restrict__ W,
             const float* __restrict__ bias, const float* __restrict__ h,
             const float* __restrict__ g, const float* __restrict__ skip,
             float* __restrict__ out) {
    __shared__ float As[16][128];
    __shared__ float Ws[16][128];
    const int br = blockIdx.x * 128;
    const int tid = threadIdx.x;
    const int tx = tid & 15, ty = tid >> 4;

    u64 acc2[8][4];
    #pragma unroll
    for (int i = 0; i < 8; i++)
        #pragma unroll
        for (int j = 0; j < 4; j++) acc2[i][j] = 0ull;

    GEMM_STAGE_AND_MAC(A, W, Nn)
    GEMM_UNPACK()

    float beta = 1.f / (1.f + expf(-skip[0]));
    float omb = 1.f - beta;
    float4 bb0 = *(const float4*)(bias + tx*4);
    float4 bb1 = *(const float4*)(bias + 64 + tx*4);
    float4 g0 = *(const float4*)(g + tx*4);
    float4 g1 = *(const float4*)(g + 64 + tx*4);

    #pragma unroll
    for (int i = 0; i < 8; i++) {
        int gr = br + ty*8 + i;
        if (gr >= Nn) continue;
        float4 h0 = *(const float4*)(h + (size_t)gr*Dd + tx*4);
        float4 h1 = *(const float4*)(h + (size_t)gr*Dd + 64 + tx*4);
        float u[8];
        u[0] = beta*(acc[i][0]+bb0.x) + omb*h0.x;
        u[1] = beta*(acc[i][1]+bb0.y) + omb*h0.y;
        u[2] = beta*(acc[i][2]+bb0.z) + omb*h0.z;
        u[3] = beta*(acc[i][3]+bb0.w) + omb*h0.w;
        u[4] = beta*(acc[i][4]+bb1.x) + omb*h1.x;
        u[5] = beta*(acc[i][5]+bb1.y) + omb*h1.y;
        u[6] = beta*(acc[i][6]+bb1.z) + omb*h1.z;
        u[7] = beta*(acc[i][7]+bb1.w) + omb*h1.w;
        float ss = 0.f;
        #pragma unroll
        for (int j = 0; j < 8; j++) ss += u[j]*u[j];
        // row lives on 16 tx-lanes (xor masks 1,2,4,8 stay in the 16-lane group)
        ss += __shfl_xor_sync(~0u, ss, 1);
        ss += __shfl_xor_sync(~0u, ss, 2);
        ss += __shfl_xor_sync(~0u, ss, 4);
        ss += __shfl_xor_sync(~0u, ss, 8);
        float inv = rsqrtf(ss * (1.0f/Dd) + EPSF);
        float4 r0, r1;
        r0.x = geluf(h0.x + g0.x*u[0]*inv);
        r0.y = geluf(h0.y + g0.y*u[1]*inv);
        r0.z = geluf(h0.z + g0.z*u[2]*inv);
        r0.w = geluf(h0.w + g0.w*u[3]*inv);
        r1.x = geluf(h1.x + g1.x*u[4]*inv);
        r1.y = geluf(h1.y + g1.y*u[5]*inv);
        r1.z = geluf(h1.z + g1.z*u[6]*inv);
        r1.w = geluf(h1.w + g1.w*u[7]*inv);
        *(float4*)(out + (size_t)gr*Dd + tx*4) = r0;
        *(float4*)(out + (size_t)gr*Dd + 64 + tx*4) = r1;
    }
}

// ---------------- GAT gather: one BLOCK per dst node, one warp per type. -------
__global__ void gat_gather_b(const int* __restrict__ csr, const int* __restrict__ off,
                             const int* __restrict__ deg, const float* __restrict__ al,
                             const float* __restrict__ ar, const float* __restrict__ xw,
                             const float* __restrict__ b, const float* __restrict__ g,
                             float* __restrict__ h) {
    int n = blockIdx.x;
    int tid = threadIdx.x;
    int t = tid >> 5, lane = tid & 31;
    int hh = lane >> 2;
    __shared__ float smf[4][128];
    __shared__ float sw[4];

    {
        int i = t*Nn + n;
        float arn = ar[(size_t)i*Hh + hh];
        // self loop (src = dst = n)
        float v = al[(size_t)i*Hh + hh] + arn;
        v = v > 0.f ? v : NEG_SLOPE*v;
        float p = expf(v);
        float s = p;
        float4 x = *(const float4*)(xw + (size_t)i*Dd + lane*4);
        float4 f = make_float4(x.x*p, x.y*p, x.z*p, x.w*p);

        int st = off[i], dg = deg[i];
        for (int j0 = 0; j0 < dg; j0 += 32) {
            int myS = (j0 + lane < dg) ? csr[st + j0 + lane] : 0;
            int cnt = min(32, dg - j0);
            for (int j = 0; j < cnt; j++) {
                int src = __shfl_sync(0xffffffffu, myS, j);
                float vv = al[((size_t)t*Nn + src)*Hh + hh] + arn;
                vv = vv > 0.f ? vv : NEG_SLOPE*vv;
                float pp = expf(vv);
                s += pp;
                float4 xx = *(const float4*)(xw + ((size_t)t*Nn + src)*Dd + lane*4);
                f.x += xx.x*pp; f.y += xx.y*pp; f.z += xx.z*pp; f.w += xx.w*pp;
            }
        }
        float inv = 1.f / s;   // s >= exp(self) > 0
        *(float4*)(&smf[t][lane*4]) = make_float4(f.x*inv, f.y*inv, f.z*inv, f.w*inv);
    }
    __syncthreads();

    // combine across types with 128 threads, then rmsnorm + residual gelu
    int d = tid;
    float a = smf[0][d] + smf[1][d] + smf[2][d] + smf[3][d]
            + b[d] + b[Dd + d] + b[2*Dd + d] + b[3*Dd + d];
    float ss = a*a;
    #pragma unroll
    for (int o = 16; o > 0; o >>= 1) ss += __shfl_xor_sync(0xffffffffu, ss, o);
    if (lane == 0) sw[t] = ss;
    __syncthreads();
    float tot = sw[0] + sw[1] + sw[2] + sw[3];
    float inv2 = rsqrtf(tot * (1.0f/Dd) + EPSF);
    int i = n*Dd + d;
    h[i] = geluf(h[i] + g[d] * a * inv2);
}

// ---------------- HGT gather: one BLOCK per dst, one warp per type. ------------
__global__ void hgt_gather_b(const int* __restrict__ csr, const int* __restrict__ off,
                             const int* __restrict__ deg, const float* __restrict__ k,
                             const float* __restrict__ q, const float* __restrict__ v,
                             const float* __restrict__ arel, const float* __restrict__ mrel,
                             const float* __restrict__ prel, float* __restrict__ out) {
    int n = blockIdx.x;
    int tid = threadIdx.x;
    int t = tid >> 5, lane = tid & 31;
    int hh = lane >> 2, qd = lane & 3;
    int qbase = lane & ~3;
    __shared__ float smacc[4][128];
    __shared__ float sms[4][8];

    {
        float4 qv = *(const float4*)(q + (size_t)n*Dd + lane*4);
        const float* A = arel + (size_t)((t*Hh + hh)*16)*16;
        float4 qA = make_float4(0,0,0,0);
        #pragma unroll
        for (int fq = 0; fq < 4; fq++) {
            float4 qb = shfl4(qv, qbase | fq);
            #pragma unroll
            for (int i = 0; i < 4; i++) {
                float4 a4 = *(const float4*)(A + (qd*4 + i)*16 + fq*4);
                float val = dot4(a4, qb);
                if (i == 0) qA.x += val;
                else if (i == 1) qA.y += val;
                else if (i == 2) qA.z += val;
                else qA.w += val;
            }
        }
        float pr = prel[t*Hh + hh] * 0.25f;   // / sqrt(16)

        float4 aggv = make_float4(0,0,0,0);
        float s = 0.f;
        int i0 = t*Nn + n, st = off[i0], dg = deg[i0];
        for (int j0 = 0; j0 < dg; j0 += 32) {
            int myS = (j0 + lane < dg) ? csr[st + j0 + lane] : 0;
            int cnt = min(32, dg - j0);
            for (int j = 0; j < cnt; j++) {
                int src = __shfl_sync(0xffffffffu, myS, j);
                float4 kv = *(const float4*)(k + (size_t)src*Dd + lane*4);
                float part = dot4(kv, qA);
                part += __shfl_xor_sync(0xffffffffu, part, 1);
                part += __shfl_xor_sync(0xffffffffu, part, 2);
                float p = expf(part * pr);
                s += p;
                float4 vv = *(const float4*)(v + (size_t)src*Dd + lane*4);
                aggv.x += vv.x*p; aggv.y += vv.y*p; aggv.z += vv.z*p; aggv.w += vv.w*p;
            }
        }
        const float* M = mrel + (size_t)((t*Hh + hh)*16)*16;
        float4 acc = make_float4(0,0,0,0);
        #pragma unroll
        for (int dq = 0; dq < 4; dq++) {
            float4 ab = shfl4(aggv, qbase | dq);
            float av[4] = {ab.x, ab.y, ab.z, ab.w};
            #pragma unroll
            for (int j = 0; j < 4; j++) {
                float4 m4 = *(const float4*)(M + (dq*4 + j)*16 + qd*4);
                float aj = av[j];
                acc.x += aj*m4.x; acc.y += aj*m4.y; acc.z += aj*m4.z; acc.w += aj*m4.w;
            }
        }
        *(float4*)(&smacc[t][lane*4]) = acc;
        if (qd == 0) sms[t][hh] = s;
    }
    __syncthreads();

    int d = tid;
    int dh = d >> 4;
    float a = smacc[0][d] + smacc[1][d] + smacc[2][d] + smacc[3][d];
    float stot = sms[0][dh] + sms[1][dh] + sms[2][dh] + sms[3][dh];
    float inv = 1.f / (stot > 0.f ? stot : 1.f);
    out[(size_t)n*Dd + d] = geluf(a * inv);
}

// ---------------- host launch ----------------
extern "C" void kernel_launch(void* const* d_in, const int* in_sizes, int n_in,
                              void* d_out, int out_size) {
    const float* zL  = (const float*)d_in[0];
    const float* zH  = (const float*)d_in[1];
    const float* xe  = (const float*)d_in[2];
    const float* W1  = (const float*)d_in[3];
    const float* as1 = (const float*)d_in[4];
    const float* ad1 = (const float*)d_in[5];
    const float* b1  = (const float*)d_in[6];
    const float* W2  = (const float*)d_in[7];
    const float* as2 = (const float*)d_in[8];
    const float* ad2 = (const float*)d_in[9];
    const float* b2  = (const float*)d_in[10];
    const float* Wk  = (const float*)d_in[11];
    const float* bk  = (const float*)d_in[12];
    const float* Wq  = (const float*)d_in[13];
    const float* bq  = (const float*)d_in[14];
    const float* Wv  = (const float*)d_in[15];
    const float* bv  = (const float*)d_in[16];
    const float* arel= (const float*)d_in[17];
    const float* mrel= (const float*)d_in[18];
    const float* prel= (const float*)d_in[19];
    const float* Wo  = (const float*)d_in[20];
    const float* bo  = (const float*)d_in[21];
    const float* skip= (const float*)d_in[22];
    const float* g1  = (const float*)d_in[23];
    const float* g2  = (const float*)d_in[24];
    const float* g3  = (const float*)d_in[25];
    const int* ei[4] = {(const int*)d_in[26], (const int*)d_in[27],
                        (const int*)d_in[28], (const int*)d_in[29]};

    float *h_, *k_, *q_, *v_, *tmp_, *al_, *ar_, *xw_;
    int *deg_, *off_, *cur_, *csr_, *bsum_;
    cudaGetSymbolAddress((void**)&h_,   g_h);
    cudaGetSymbolAddress((void**)&k_,   g_k);
    cudaGetSymbolAddress((void**)&q_,   g_q);
    cudaGetSymbolAddress((void**)&v_,   g_v);
    cudaGetSymbolAddress((void**)&tmp_, g_tmp);
    cudaGetSymbolAddress((void**)&al_,  g_al);
    cudaGetSymbolAddress((void**)&ar_,  g_ar);
    cudaGetSymbolAddress((void**)&xw_,  g_xw);
    cudaGetSymbolAddress((void**)&deg_, g_deg);
    cudaGetSymbolAddress((void**)&off_, g_off);
    cudaGetSymbolAddress((void**)&cur_, g_cur);
    cudaGetSymbolAddress((void**)&csr_, g_csr);
    cudaGetSymbolAddress((void**)&bsum_,g_bsum);

    const int nd = Nn*Dd;
    const int TPB = 256;
    const int gemm_grid = (Nn + 127) / 128;

    add3k<<<(nd/4 + TPB-1)/TPB, TPB>>>((const float4*)zL, (const float4*)zH,
                                       (const float4*)xe, (float4*)h_, nd/4);

    // --- CSR build (shared by GAT layers and HGT) ---
    zeroint<<<(TN + TPB-1)/TPB, TPB>>>(deg_, TN);
    deg_k<<<(E4 + TPB-1)/TPB, TPB>>>(ei[0], ei[1], ei[2], ei[3], deg_);
    scan_pre<<<SCAN_NB, 1024>>>(deg_, bsum_);
    scan_mid<<<1, 256>>>(bsum_);
    scan_post<<<SCAN_NB, 1024>>>(deg_, bsum_, off_, cur_);
    fill_k<<<(E4 + TPB-1)/TPB, TPB>>>(ei[0], ei[1], ei[2], ei[3], cur_, csr_);

    // --- two hetero-GAT layers ---
    const float* Ws[2]  = {W1, W2};
    const float* ass[2] = {as1, as2};
    const float* ads[2] = {ad1, ad2};
    const float* bs[2]  = {b1, b2};
    const float* gs[2]  = {g1, g2};
    for (int L = 0; L < 2; L++) {
        gemm_ff<true><<<dim3(gemm_grid, Tt), TPB>>>(h_, Ws[L], nullptr, xw_,
                                                    ass[L], ads[L], al_, ar_, Nn);
        gat_gather_b<<<Nn, 128>>>(csr_, off_, deg_, al_, ar_, xw_,
                                  bs[L], gs[L], h_);
    }

    // --- HGT layer ---
    gemm_ff<false><<<dim3(gemm_grid,1), TPB>>>(h_, Wk, bk, k_, nullptr, nullptr, nullptr, nullptr, Nn);
    gemm_ff<false><<<dim3(gemm_grid,1), TPB>>>(h_, Wq, bq, q_, nullptr, nullptr, nullptr, nullptr, Nn);
    gemm_ff<false><<<dim3(gemm_grid,1), TPB>>>(h_, Wv, bv, v_, nullptr, nullptr, nullptr, nullptr, Nn);
    hgt_gather_b<<<Nn, 128>>>(csr_, off_, deg_, k_, q_, v_, arel, mrel, prel, tmp_);
    gemm_wo_post<<<gemm_grid, TPB>>>(tmp_, Wo, bo, h_, g3, skip, (float*)d_out);
}